// round 1
// baseline (speedup 1.0000x reference)
#include <cuda_runtime.h>
#include <math_constants.h>

// Problem constants (fixed by the reference)
#define BB 2
#define TT 512
#define EE 1024
#define SS 2048
#define AA 30

// Scratch for precomputed head scores: relu(x @ W + b), shape (B*T)
__device__ float g_scores[BB * TT];

// ---------------------------------------------------------------------------
// Kernel 1: scores[b,t] = relu(dot(x[b,t,:], W) + bias)
// One warp per row. 1024 floats per row -> 8 float4 per lane.
// ---------------------------------------------------------------------------
__global__ void score_kernel(const float* __restrict__ x,
                             const float* __restrict__ W,
                             const float* __restrict__ bias) {
    const int row  = blockIdx.x * 8 + (threadIdx.x >> 5);   // B*T = 1024 rows
    const int lane = threadIdx.x & 31;

    const float4* __restrict__ xr = reinterpret_cast<const float4*>(x + (size_t)row * EE);
    const float4* __restrict__ w4 = reinterpret_cast<const float4*>(W);

    float acc = 0.0f;
#pragma unroll
    for (int i = 0; i < 8; ++i) {
        const float4 xv = xr[lane + i * 32];
        const float4 wv = w4[lane + i * 32];
        acc += xv.x * wv.x + xv.y * wv.y + xv.z * wv.z + xv.w * wv.w;
    }
#pragma unroll
    for (int off = 16; off; off >>= 1)
        acc += __shfl_xor_sync(0xffffffffu, acc, off);

    if (lane == 0)
        g_scores[row] = fmaxf(acc + bias[0], 0.0f);
}

// ---------------------------------------------------------------------------
// Kernel 2: per (s, b) block.
//   warp 0: softmax over the <=30 valid scores -> smem p[]
//   all 256 threads: out[b,s, tid*4 .. tid*4+3] = sum_j p[j] * x[b, t0+j, ...]
// ---------------------------------------------------------------------------
__global__ __launch_bounds__(256)
void span_kernel(const float* __restrict__ x,
                 const int* __restrict__ start,
                 const int* __restrict__ end,
                 float* __restrict__ out) {
    const int s = blockIdx.x;
    const int b = blockIdx.y;

    const int t0 = start[s];
    const int w  = end[s] - t0 + 1;   // 1..30, and t0+w-1 <= T-1 guaranteed

    __shared__ float p[AA];

    const int tid = threadIdx.x;
    if (tid < 32) {
        float sc = (tid < w) ? g_scores[b * TT + t0 + tid] : -CUDART_INF_F;
        float m = sc;
#pragma unroll
        for (int off = 16; off; off >>= 1)
            m = fmaxf(m, __shfl_xor_sync(0xffffffffu, m, off));
        float e = (tid < w) ? __expf(sc - m) : 0.0f;
        float sum = e;
#pragma unroll
        for (int off = 16; off; off >>= 1)
            sum += __shfl_xor_sync(0xffffffffu, sum, off);
        if (tid < AA)
            p[tid] = e / sum;
    }
    __syncthreads();

    // Each thread owns one float4 column of E (256 * 4 = 1024).
    const float4* __restrict__ xb =
        reinterpret_cast<const float4*>(x + ((size_t)b * TT + t0) * EE);

    float4 acc = make_float4(0.0f, 0.0f, 0.0f, 0.0f);

    int j = 0;
    // unroll-by-2 for a bit of MLP; remainder handled after
#pragma unroll 1
    for (; j + 2 <= w; j += 2) {
        const float p0 = p[j];
        const float p1 = p[j + 1];
        const float4 v0 = xb[(size_t)(j)     * (EE / 4) + tid];
        const float4 v1 = xb[(size_t)(j + 1) * (EE / 4) + tid];
        acc.x += p0 * v0.x + p1 * v1.x;
        acc.y += p0 * v0.y + p1 * v1.y;
        acc.z += p0 * v0.z + p1 * v1.z;
        acc.w += p0 * v0.w + p1 * v1.w;
    }
    if (j < w) {
        const float pj = p[j];
        const float4 v = xb[(size_t)j * (EE / 4) + tid];
        acc.x += pj * v.x;
        acc.y += pj * v.y;
        acc.z += pj * v.z;
        acc.w += pj * v.w;
    }

    float4* __restrict__ o =
        reinterpret_cast<float4*>(out + ((size_t)b * SS + s) * EE);
    o[tid] = acc;
}

// ---------------------------------------------------------------------------
// Launch
// Inputs (metadata order): x (B,T,E) f32, W (E,1) f32, b (1,) f32,
//                          start (S,) i32, end (S,) i32
// Output: (B, S, E) f32
// ---------------------------------------------------------------------------
extern "C" void kernel_launch(void* const* d_in, const int* in_sizes, int n_in,
                              void* d_out, int out_size) {
    const float* x     = (const float*)d_in[0];
    const float* W     = (const float*)d_in[1];
    const float* bias  = (const float*)d_in[2];
    const int*   start = (const int*)d_in[3];
    const int*   end   = (const int*)d_in[4];
    float*       out   = (float*)d_out;

    // Kernel 1: B*T = 1024 rows, 8 warps/block -> 128 blocks
    score_kernel<<<(BB * TT) / 8, 256>>>(x, W, bias);

    // Kernel 2: one block per (span, batch)
    dim3 grid(SS, BB);
    span_kernel<<<grid, 256>>>(x, start, end, out);
}